// round 1
// baseline (speedup 1.0000x reference)
#include <cuda_runtime.h>

#define NQ   512
#define NK   1024
#define DIMC 256
#define NH   8
#define HD   32
#define RPE  512
#define NSEG (RPE + 1)

// ---------------- scratch (static __device__ — allocation-free) ----------------
static __device__ float          g_tsort[RPE];
static __device__ float          g_A[NH * NSEG];
static __device__ float          g_C[NH * NSEG];
static __device__ unsigned short g_seg[NQ * NK];
static __device__ float          g_q[NQ * DIMC];
static __device__ float          g_k[NK * DIMC];
static __device__ float          g_v[NK * DIMC];
static __device__ float          g_S[NH * NQ * NK];   // 16 MB: scores -> probs in place
static __device__ float          g_x[NQ * DIMC];

// =============================================================================
// Kernel 1: build piecewise-linear CPB bias tables.
// bias_h(m) = sum_r relu(m*w1_r + b1_r) * W2[r,h] is piecewise linear in m with
// breakpoints t_r = -b1_r/w1_r. For segment s (= #breakpoints <= m):
//   bias_h(m) = A[h][s]*m + C[h][s]
// A[s] = mTot + prefix_{p<s} e[p] with e[p] = plus ? ca : -ca, mTot = sum of
// "minus"-type ca (terms active for m below their breakpoint).
// =============================================================================
__global__ void pwl_build(const float* __restrict__ W1, const float* __restrict__ b1,
                          const float* __restrict__ W2) {
    __shared__ float key[RPE];
    __shared__ int   sidx[RPE];
    __shared__ float sW1[RPE], sb1[RPE];
    __shared__ float sW2[RPE * NH];

    const int tid = threadIdx.x;
    float w = W1[tid], b = b1[tid];
    float t;
    if (w != 0.0f) t = -b / w;
    else t = (b > 0.0f) ? -__int_as_float(0x7f800000) : __int_as_float(0x7f800000);
    key[tid] = t;
    sidx[tid] = tid;
    sW1[tid] = w;
    sb1[tid] = b;
#pragma unroll
    for (int h = 0; h < NH; h++) sW2[tid * NH + h] = W2[tid * NH + h];
    __syncthreads();

    // bitonic sort ascending (512 elements, 512 threads)
    for (int k = 2; k <= RPE; k <<= 1) {
        for (int j = k >> 1; j > 0; j >>= 1) {
            int ixj = tid ^ j;
            if (ixj > tid) {
                bool up = ((tid & k) == 0);
                float a = key[tid], c = key[ixj];
                bool sw = up ? (a > c) : (a < c);
                if (sw) {
                    key[tid] = c; key[ixj] = a;
                    int ia = sidx[tid]; sidx[tid] = sidx[ixj]; sidx[ixj] = ia;
                }
            }
            __syncthreads();
        }
    }
    g_tsort[tid] = key[tid];

    // per-head warp scan (warps 0..7); lane handles 16 sorted positions
    const int warp = tid >> 5, lane = tid & 31;
    if (warp < NH) {
        const int h = warp;
        float eA[16], eC[16];
        float leA = 0.f, leC = 0.f, mA = 0.f, mC = 0.f;
#pragma unroll
        for (int pp = 0; pp < 16; pp++) {
            int p = lane * 16 + pp;
            int r = sidx[p];
            float w1 = sW1[r], bb = sb1[r], w2 = sW2[r * NH + h];
            float ca, cc; bool plus;
            if (w1 > 0.f)      { plus = true;  ca = w1 * w2; cc = bb * w2; }
            else if (w1 < 0.f) { plus = false; ca = w1 * w2; cc = bb * w2; }
            else               { plus = true;  ca = 0.f;     cc = (bb > 0.f) ? bb * w2 : 0.f; }
            float ea = plus ? ca : -ca;
            float ec = plus ? cc : -cc;
            eA[pp] = ea; eC[pp] = ec;
            leA += ea; leC += ec;
            if (!plus) { mA += ca; mC += cc; }
        }
        // inclusive warp scan of lane sums -> exclusive
        float inA = leA, inC = leC;
#pragma unroll
        for (int o = 1; o < 32; o <<= 1) {
            float ta = __shfl_up_sync(0xffffffffu, inA, o);
            float tc = __shfl_up_sync(0xffffffffu, inC, o);
            if (lane >= o) { inA += ta; inC += tc; }
        }
        float exA = inA - leA, exC = inC - leC;
        // total of minus-type contributions (all lanes)
#pragma unroll
        for (int o = 16; o > 0; o >>= 1) {
            mA += __shfl_xor_sync(0xffffffffu, mA, o);
            mC += __shfl_xor_sync(0xffffffffu, mC, o);
        }
        if (lane == 0) { g_A[h * NSEG] = mA; g_C[h * NSEG] = mC; }
        float runA = exA, runC = exC;
#pragma unroll
        for (int pp = 0; pp < 16; pp++) {
            runA += eA[pp]; runC += eC[pp];
            int s = lane * 16 + pp + 1;
            g_A[h * NSEG + s] = mA + runA;
            g_C[h * NSEG + s] = mC + runC;
        }
    }
}

// =============================================================================
// Kernel 2: segment index per (q,k) — head independent. 1 binary search each.
// =============================================================================
__global__ void seg_kernel(const float* __restrict__ am) {
    __shared__ float ts[RPE];
    int t = threadIdx.x;
    ts[t] = g_tsort[t];
    ts[t + 256] = g_tsort[t + 256];
    __syncthreads();
    int i = blockIdx.x * 256 + t;
    float m = am[i];
    int lo = 0, hi = RPE;
#pragma unroll 9
    while (lo < hi) {
        int mid = (lo + hi) >> 1;
        if (ts[mid] <= m) lo = mid + 1; else hi = mid;
    }
    g_seg[i] = (unsigned short)lo;
}

// =============================================================================
// Shared GEMM body: C[M,256] = (A[M,256] @ W[256,256] + bias) * scale
// 64x64 tile / block, 256 threads, 4x4 per thread, BK=16.
// =============================================================================
__device__ __forceinline__ void gemm_body(const float* __restrict__ A, const float* __restrict__ W,
                                          const float* __restrict__ bias, float* __restrict__ C,
                                          int M, float scale) {
    __shared__ float As[16][68];
    __shared__ float Ws[16][68];
    int bm = blockIdx.y * 64;
    if (bm >= M) return;                     // uniform across block
    int bn = blockIdx.x * 64;
    int t = threadIdx.x;
    int tx = t & 15, ty = t >> 4;
    int ra = t >> 2, ka = (t & 3) * 4;       // A-tile load mapping
    int kw = t >> 4, nw = (t & 15) * 4;      // W-tile load mapping
    float acc[4][4] = {};
    for (int k0 = 0; k0 < DIMC; k0 += 16) {
        float4 av = *(const float4*)&A[(bm + ra) * DIMC + k0 + ka];
        As[ka + 0][ra] = av.x; As[ka + 1][ra] = av.y;
        As[ka + 2][ra] = av.z; As[ka + 3][ra] = av.w;
        *(float4*)&Ws[kw][nw] = *(const float4*)&W[(k0 + kw) * DIMC + bn + nw];
        __syncthreads();
#pragma unroll
        for (int kk = 0; kk < 16; kk++) {
            float4 a4 = *(const float4*)&As[kk][ty * 4];
            float4 w4 = *(const float4*)&Ws[kk][tx * 4];
            float aa[4] = {a4.x, a4.y, a4.z, a4.w};
            float ww[4] = {w4.x, w4.y, w4.z, w4.w};
#pragma unroll
            for (int i = 0; i < 4; i++)
#pragma unroll
                for (int j = 0; j < 4; j++)
                    acc[i][j] += aa[i] * ww[j];
        }
        __syncthreads();
    }
#pragma unroll
    for (int i = 0; i < 4; i++) {
        int row = bm + ty * 4 + i;
        float4 o;
        o.x = (acc[i][0] + bias[bn + tx * 4 + 0]) * scale;
        o.y = (acc[i][1] + bias[bn + tx * 4 + 1]) * scale;
        o.z = (acc[i][2] + bias[bn + tx * 4 + 2]) * scale;
        o.w = (acc[i][3] + bias[bn + tx * 4 + 3]) * scale;
        *(float4*)&C[row * DIMC + bn + tx * 4] = o;
    }
}

// Kernel 3: fused Q/K/V projections (blockIdx.z selects which)
__global__ void gemm_qkv(const float* __restrict__ q_in, const float* __restrict__ k_in,
                         const float* __restrict__ v_in,
                         const float* __restrict__ Wq, const float* __restrict__ bq_,
                         const float* __restrict__ Wk, const float* __restrict__ bk_,
                         const float* __restrict__ Wv, const float* __restrict__ bv_) {
    const float *A, *W, *B; float *Cp; int M; float sc;
    if (blockIdx.z == 0)      { A = q_in; W = Wq; B = bq_; Cp = g_q; M = NQ; sc = 0.17677669529663687f; }
    else if (blockIdx.z == 1) { A = k_in; W = Wk; B = bk_; Cp = g_k; M = NK; sc = 1.0f; }
    else                      { A = v_in; W = Wv; B = bv_; Cp = g_v; M = NK; sc = 1.0f; }
    gemm_body(A, W, B, Cp, M, sc);
}

// Kernel 7: output projection
__global__ void gemm_final(const float* __restrict__ Wp, const float* __restrict__ bp_,
                           float* __restrict__ out) {
    gemm_body(g_x, Wp, bp_, out, NQ, 1.0f);
}

// =============================================================================
// Kernel 4: scores S[h][q][k] = q·k + A[seg]*m + C[seg] - 100*pad[k]
// 64q x 64k tile per block per head; K=32 (single pass).
// =============================================================================
__global__ void scores_kernel(const float* __restrict__ am, const float* __restrict__ pad) {
    __shared__ float Qs[64][33];
    __shared__ float Ks[64][33];
    __shared__ float Ah[NSEG], Ch[NSEG];
    __shared__ float padp[64];

    const int h  = blockIdx.z;
    const int bq = blockIdx.y * 64;
    const int bk = blockIdx.x * 64;
    const int t  = threadIdx.x;

    {
        int r = t >> 2, c = (t & 3) * 8;
        const float* qp = &g_q[(bq + r) * DIMC + h * HD + c];
        float4 a = *(const float4*)qp;
        float4 b = *(const float4*)(qp + 4);
        Qs[r][c + 0] = a.x; Qs[r][c + 1] = a.y; Qs[r][c + 2] = a.z; Qs[r][c + 3] = a.w;
        Qs[r][c + 4] = b.x; Qs[r][c + 5] = b.y; Qs[r][c + 6] = b.z; Qs[r][c + 7] = b.w;
        const float* kp = &g_k[(bk + r) * DIMC + h * HD + c];
        float4 c0 = *(const float4*)kp;
        float4 c1 = *(const float4*)(kp + 4);
        Ks[r][c + 0] = c0.x; Ks[r][c + 1] = c0.y; Ks[r][c + 2] = c0.z; Ks[r][c + 3] = c0.w;
        Ks[r][c + 4] = c1.x; Ks[r][c + 5] = c1.y; Ks[r][c + 6] = c1.z; Ks[r][c + 7] = c1.w;
    }
    for (int i = t; i < NSEG; i += 256) { Ah[i] = g_A[h * NSEG + i]; Ch[i] = g_C[h * NSEG + i]; }
    if (t < 64) padp[t] = pad[bk + t] * (-100.0f);
    __syncthreads();

    const int tx = t & 15, ty = t >> 4;
    float acc[4][4] = {};
#pragma unroll 8
    for (int d = 0; d < HD; d++) {
        float qa[4], kb[4];
#pragma unroll
        for (int i = 0; i < 4; i++) qa[i] = Qs[ty * 4 + i][d];
#pragma unroll
        for (int j = 0; j < 4; j++) kb[j] = Ks[tx * 4 + j][d];
#pragma unroll
        for (int i = 0; i < 4; i++)
#pragma unroll
            for (int j = 0; j < 4; j++)
                acc[i][j] += qa[i] * kb[j];
    }

#pragma unroll
    for (int i = 0; i < 4; i++) {
        int qg = bq + ty * 4 + i;
        const float*          amrow  = &am[qg * NK + bk + tx * 4];
        const unsigned short* segrow = &g_seg[qg * NK + bk + tx * 4];
        float4 out;
        float* o = (float*)&out;
#pragma unroll
        for (int j = 0; j < 4; j++) {
            float m = amrow[j];
            int   s = segrow[j];
            o[j] = acc[i][j] + fmaf(Ah[s], m, Ch[s]) + padp[tx * 4 + j];
        }
        *(float4*)&g_S[((h * NQ) + qg) * NK + bk + tx * 4] = out;
    }
}

// =============================================================================
// Kernel 5: row softmax over k (1024) — one warp per (h,q) row, in place.
// =============================================================================
__global__ void softmax_kernel() {
    int warp = threadIdx.x >> 5, lane = threadIdx.x & 31;
    int row = blockIdx.x * 8 + warp;                 // 0..4095
    float4* p = (float4*)&g_S[(size_t)row * NK];
    float4 v[8];
    float mx = -1e30f;
#pragma unroll
    for (int i = 0; i < 8; i++) {
        v[i] = p[lane + 32 * i];
        mx = fmaxf(mx, fmaxf(fmaxf(v[i].x, v[i].y), fmaxf(v[i].z, v[i].w)));
    }
#pragma unroll
    for (int o = 16; o > 0; o >>= 1) mx = fmaxf(mx, __shfl_xor_sync(0xffffffffu, mx, o));
    float sum = 0.f;
#pragma unroll
    for (int i = 0; i < 8; i++) {
        v[i].x = __expf(v[i].x - mx);
        v[i].y = __expf(v[i].y - mx);
        v[i].z = __expf(v[i].z - mx);
        v[i].w = __expf(v[i].w - mx);
        sum += (v[i].x + v[i].y) + (v[i].z + v[i].w);
    }
#pragma unroll
    for (int o = 16; o > 0; o >>= 1) sum += __shfl_xor_sync(0xffffffffu, sum, o);
    float inv = 1.0f / sum;
#pragma unroll
    for (int i = 0; i < 8; i++) {
        v[i].x *= inv; v[i].y *= inv; v[i].z *= inv; v[i].w *= inv;
        p[lane + 32 * i] = v[i];
    }
}

// =============================================================================
// Kernel 6: O[h] = P[h] @ V[h]  -> g_x[q][h*32+d].  32q x 32d tile / block.
// =============================================================================
__global__ void pv_kernel() {
    __shared__ float Ps[32][68];
    __shared__ float Vs[64][32];
    const int h  = blockIdx.y;
    const int bq = blockIdx.x * 32;
    const int t  = threadIdx.x;
    const int ty = t >> 3, tx = t & 7;
    float4 acc = {0.f, 0.f, 0.f, 0.f};
    for (int kc = 0; kc < NK; kc += 64) {
#pragma unroll
        for (int u = 0; u < 2; u++) {
            int fid = t + u * 256;
            int r = fid >> 4, c4 = (fid & 15) * 4;
            float4 a = *(const float4*)&g_S[((size_t)(h * NQ) + bq + r) * NK + kc + c4];
            Ps[r][c4 + 0] = a.x; Ps[r][c4 + 1] = a.y; Ps[r][c4 + 2] = a.z; Ps[r][c4 + 3] = a.w;
            int k = fid >> 3, d4 = (fid & 7) * 4;
            *(float4*)&Vs[k][d4] = *(const float4*)&g_v[(kc + k) * DIMC + h * HD + d4];
        }
        __syncthreads();
#pragma unroll 8
        for (int k = 0; k < 64; k++) {
            float pv = Ps[ty][k];
            float4 vv = *(const float4*)&Vs[k][tx * 4];
            acc.x += pv * vv.x; acc.y += pv * vv.y;
            acc.z += pv * vv.z; acc.w += pv * vv.w;
        }
        __syncthreads();
    }
    *(float4*)&g_x[(bq + ty) * DIMC + h * HD + tx * 4] = acc;
}

// =============================================================================
extern "C" void kernel_launch(void* const* d_in, const int* in_sizes, int n_in,
                              void* d_out, int out_size) {
    const float* query = (const float*)d_in[0];
    const float* kin   = (const float*)d_in[1];
    const float* vin   = (const float*)d_in[2];
    const float* pad   = (const float*)d_in[3];
    const float* am    = (const float*)d_in[4];
    const float* Wq    = (const float*)d_in[5];
    const float* bq    = (const float*)d_in[6];
    const float* Wk    = (const float*)d_in[7];
    const float* bk    = (const float*)d_in[8];
    const float* Wv    = (const float*)d_in[9];
    const float* bv    = (const float*)d_in[10];
    const float* Wp    = (const float*)d_in[11];
    const float* bp    = (const float*)d_in[12];
    const float* W1    = (const float*)d_in[13];
    const float* b1    = (const float*)d_in[14];
    const float* W2    = (const float*)d_in[15];
    float* out = (float*)d_out;

    pwl_build<<<1, 512>>>(W1, b1, W2);
    seg_kernel<<<(NQ * NK) / 256, 256>>>(am);
    gemm_qkv<<<dim3(4, 16, 3), 256>>>(query, kin, vin, Wq, bq, Wk, bk, Wv, bv);
    scores_kernel<<<dim3(16, 8, 8), 256>>>(am, pad);
    softmax_kernel<<<512, 256>>>();
    pv_kernel<<<dim3(16, 8), 256>>>();
    gemm_final<<<dim3(4, 8), 256>>>(Wp, bp, out);
}